// round 3
// baseline (speedup 1.0000x reference)
#include <cuda_runtime.h>

// Problem constants
#define IN_F   2048
#define OUT_F  4096
#define BATCHN 131072

#define NSLICE 128            // weight row slices (4096/32 rows each)
#define IN_F4  (IN_F / 4)     // 512 float4 columns

// Scratch (static device globals — allocation-free). Fully overwritten every
// launch => graph-replay deterministic.
__device__ float4 g_partial4[NSLICE * IN_F4];  // per-slice column sums (1 MiB)
__device__ float  g_wsum[IN_F];                // weight.sum(axis=0)
__device__ float  g_bsum;                      // bias.sum()

// ---------------------------------------------------------------------------
// Kernel 1: partial column-sums of weight, vectorized.
// grid = (IN_F4/256 = 2, NSLICE = 128), block = 256.
// Block (bx, by): sums 32 rows [by*32, by*32+32) for float4-columns
// [bx*256, bx*256+256). Fully unrolled -> 32 independent 16B loads in flight
// per thread (MLP ~= 32, near the per-warp outstanding-LDG cap). Each row
// access is 4 KB contiguous per block.
// ---------------------------------------------------------------------------
__global__ __launch_bounds__(256) void reduce_weight_kernel(const float4* __restrict__ w) {
    const int c  = blockIdx.x * 256 + threadIdx.x;   // float4 column
    const int r0 = blockIdx.y * 32;                  // first row of slice
    const float4* wp = w + (size_t)r0 * IN_F4 + c;

    float4 s0 = make_float4(0.f, 0.f, 0.f, 0.f);
    float4 s1 = make_float4(0.f, 0.f, 0.f, 0.f);
    #pragma unroll
    for (int r = 0; r < 32; r += 2) {
        float4 a = wp[(size_t)r * IN_F4];
        float4 b = wp[(size_t)(r + 1) * IN_F4];
        s0.x += a.x; s0.y += a.y; s0.z += a.z; s0.w += a.w;
        s1.x += b.x; s1.y += b.y; s1.z += b.z; s1.w += b.w;
    }
    s0.x += s1.x; s0.y += s1.y; s0.z += s1.z; s0.w += s1.w;
    g_partial4[blockIdx.y * IN_F4 + c] = s0;
}

// ---------------------------------------------------------------------------
// Kernel 2: fold NSLICE partials -> w_sum; block 2 reduces bias -> b_sum.
// grid = 3, block = 256. Fixed-order summation => deterministic.
// Partials are L2-resident (written immediately before, 1 MiB << 126 MB L2).
// ---------------------------------------------------------------------------
__global__ __launch_bounds__(256) void finalize_kernel(const float* __restrict__ bias) {
    if (blockIdx.x < 2) {
        const int c = blockIdx.x * 256 + threadIdx.x;   // float4 column
        float4 s0 = make_float4(0.f, 0.f, 0.f, 0.f);
        float4 s1 = make_float4(0.f, 0.f, 0.f, 0.f);
        #pragma unroll 8
        for (int p = 0; p < NSLICE; p += 2) {
            float4 a = g_partial4[p * IN_F4 + c];
            float4 b = g_partial4[(p + 1) * IN_F4 + c];
            s0.x += a.x; s0.y += a.y; s0.z += a.z; s0.w += a.w;
            s1.x += b.x; s1.y += b.y; s1.z += b.z; s1.w += b.w;
        }
        s0.x += s1.x; s0.y += s1.y; s0.z += s1.z; s0.w += s1.w;
        reinterpret_cast<float4*>(g_wsum)[c] = s0;
    } else {
        // bias reduction: 4096 elements, deterministic tree.
        __shared__ float red[256];
        float s = 0.0f;
        #pragma unroll
        for (int i = 0; i < OUT_F / 256; ++i) {
            s += bias[i * 256 + threadIdx.x];
        }
        red[threadIdx.x] = s;
        __syncthreads();
        #pragma unroll
        for (int stride = 128; stride > 0; stride >>= 1) {
            if (threadIdx.x < stride) red[threadIdx.x] += red[threadIdx.x + stride];
            __syncthreads();
        }
        if (threadIdx.x == 0) g_bsum = red[0];
    }
}

// ---------------------------------------------------------------------------
// Kernel 3: out[row] = dot(x[row,:], w_sum) + b_sum.   (unchanged — 7.35 TB/s)
// Warp-per-row. block = 256 (8 warps), grid = BATCH/8 = 16384.
// ---------------------------------------------------------------------------
__global__ __launch_bounds__(256) void gemv_kernel(const float* __restrict__ x,
                                                   float* __restrict__ out) {
    __shared__ float4 sw[IN_F4];   // 8 KB
    __shared__ float sb;

    const int tid = threadIdx.x;
    #pragma unroll
    for (int i = 0; i < IN_F4 / 256; ++i) {
        sw[i * 256 + tid] = reinterpret_cast<const float4*>(g_wsum)[i * 256 + tid];
    }
    if (tid == 0) sb = g_bsum;
    __syncthreads();

    const int warp = tid >> 5;
    const int lane = tid & 31;
    const int row  = blockIdx.x * 8 + warp;

    const float4* xr = reinterpret_cast<const float4*>(x + (size_t)row * IN_F);

    float acc = 0.0f;
    #pragma unroll
    for (int i = 0; i < 16; ++i) {          // 16 * 32 lanes * 4 floats = 2048
        const float4 xv = xr[i * 32 + lane];
        const float4 wv = sw[i * 32 + lane];
        acc += xv.x * wv.x + xv.y * wv.y + xv.z * wv.z + xv.w * wv.w;
    }

    #pragma unroll
    for (int off = 16; off > 0; off >>= 1) {
        acc += __shfl_xor_sync(0xFFFFFFFFu, acc, off);
    }
    if (lane == 0) {
        out[row] = acc + sb;
    }
}

// ---------------------------------------------------------------------------
extern "C" void kernel_launch(void* const* d_in, const int* in_sizes, int n_in,
                              void* d_out, int out_size) {
    const float* x      = (const float*)d_in[0];  // (131072, 2048)
    const float* weight = (const float*)d_in[1];  // (4096, 2048)
    const float* bias   = (const float*)d_in[2];  // (4096,)
    float* out = (float*)d_out;                   // (131072, 1)

    (void)in_sizes; (void)n_in; (void)out_size;

    dim3 g1(IN_F4 / 256, NSLICE);
    reduce_weight_kernel<<<g1, 256>>>(reinterpret_cast<const float4*>(weight));
    finalize_kernel<<<3, 256>>>(bias);
    gemv_kernel<<<BATCHN / 8, 256>>>(x, out);
}

// round 4
// speedup vs baseline: 1.0019x; 1.0019x over previous
#include <cuda_runtime.h>

// Problem constants
#define IN_F    2048
#define OUT_F   4096
#define BATCHN  131072
#define IN_F4   (IN_F / 4)        // 512 float4 columns

// Fused-kernel block layout
#define NFOLD   16                // folder blocks (bids 0..15)
#define BID_BIAS 16               // bias block
#define NRED    512               // weight reducer blocks (bids 17..528)
#define BID_RED0 17
#define BID_GEMV0 (BID_RED0 + NRED)           // 529
#define NGEMV   (BATCHN / 8)                  // 16384
#define GRID_TOTAL (BID_GEMV0 + NGEMV)

#define NSLICE  256               // 4096 rows / 16 rows per reducer slice

// Scratch globals (allocation-free). Everything below is fully rewritten
// every launch => graph-replay deterministic.
__device__ float4 g_partial4[NSLICE * IN_F4];   // 2 MiB partial column sums
__device__ float  g_wsum[IN_F];
__device__ float  g_bsum;
__device__ int    g_red_done;     // -> NRED
__device__ int    g_fold_done;    // -> NFOLD + 1

// ---------------------------------------------------------------------------
__global__ void init_kernel() {
    g_red_done  = 0;
    g_fold_done = 0;
}

// ---------------------------------------------------------------------------
// Fused kernel. 256 threads per block.
//   bids [0,16):       folders — wait for all reducers, fold 32 f4-cols each
//   bid  16:           bias sum
//   bids [17,529):     weight reducers (16-row x 256-f4col slice)
//   bids [529, ...):   gemv, warp-per-row (prefetch x, wait for fold, compute)
// ---------------------------------------------------------------------------
__global__ __launch_bounds__(256) void fused_kernel(const float4* __restrict__ w4,
                                                    const float*  __restrict__ x,
                                                    const float*  __restrict__ bias,
                                                    float* __restrict__ out) {
    __shared__ float4 sw[IN_F4];      // 8 KB (gemv staging; folders reuse a slice)
    const int tid = threadIdx.x;
    const int bid = blockIdx.x;

    // ======================== GEMV blocks (hot path) ========================
    if (bid >= BID_GEMV0) {
        const int gvb = bid - BID_GEMV0;
        const int warp = tid >> 5;
        const int lane = tid & 31;
        const int row  = gvb * 8 + warp;
        const float4* xr = reinterpret_cast<const float4*>(x + (size_t)row * IN_F);

        // Prefetch this block's 64 KB of x into L2 BEFORE waiting on the fold.
        // (Overlaps x DRAM traffic with the weight reduction for wave-1 blocks.)
        {
            const char* pfx = reinterpret_cast<const char*>(x)
                            + (size_t)gvb * 8 * IN_F * sizeof(float)
                            + (size_t)tid * 256;
            asm volatile("prefetch.global.L2 [%0];" :: "l"(pfx));
            asm volatile("prefetch.global.L2 [%0];" :: "l"(pfx + 128));
        }

        // Wait for w_sum + b_sum to be published.
        if (tid == 0) {
            while (*(volatile int*)&g_fold_done != (NFOLD + 1)) {
                __nanosleep(64);
            }
            __threadfence();
        }
        __syncthreads();

        // Stage w_sum into shared.
        #pragma unroll
        for (int i = 0; i < IN_F4 / 256; ++i) {
            sw[i * 256 + tid] = reinterpret_cast<const float4*>(g_wsum)[i * 256 + tid];
        }
        __syncthreads();
        const float bsum = g_bsum;

        float acc = 0.0f;
        #pragma unroll
        for (int i = 0; i < 16; ++i) {          // 16 * 32 lanes * 4 = 2048
            const float4 xv = xr[i * 32 + lane];
            const float4 wv = sw[i * 32 + lane];
            acc += xv.x * wv.x + xv.y * wv.y + xv.z * wv.z + xv.w * wv.w;
        }
        #pragma unroll
        for (int off = 16; off > 0; off >>= 1) {
            acc += __shfl_xor_sync(0xFFFFFFFFu, acc, off);
        }
        if (lane == 0) out[row] = acc + bsum;
        return;
    }

    // ======================== Weight reducer blocks ========================
    if (bid >= BID_RED0) {
        const int r  = bid - BID_RED0;
        const int cg = r & 1;              // column group (0/1)
        const int s  = r >> 1;             // row slice, 16 rows
        const int c  = cg * 256 + tid;     // float4 column
        const float4* wp = w4 + (size_t)(s * 16) * IN_F4 + c;

        float4 acc = make_float4(0.f, 0.f, 0.f, 0.f);
        #pragma unroll
        for (int b = 0; b < 2; ++b) {      // two batches of 8 in-flight loads
            float4 t[8];
            #pragma unroll
            for (int i = 0; i < 8; ++i) {
                t[i] = wp[(size_t)(b * 8 + i) * IN_F4];
            }
            #pragma unroll
            for (int i = 0; i < 8; ++i) {
                acc.x += t[i].x; acc.y += t[i].y; acc.z += t[i].z; acc.w += t[i].w;
            }
        }
        g_partial4[s * IN_F4 + c] = acc;
        __threadfence();
        __syncthreads();
        if (tid == 0) atomicAdd(&g_red_done, 1);
        return;
    }

    // ======================== Bias block ========================
    if (bid == BID_BIAS) {
        __shared__ float red[256];
        float s = 0.0f;
        #pragma unroll
        for (int i = 0; i < OUT_F / 256; ++i) s += bias[i * 256 + tid];
        red[tid] = s;
        __syncthreads();
        #pragma unroll
        for (int stride = 128; stride > 0; stride >>= 1) {
            if (tid < stride) red[tid] += red[tid + stride];
            __syncthreads();
        }
        if (tid == 0) {
            g_bsum = red[0];
            __threadfence();
            atomicAdd(&g_fold_done, 1);
        }
        return;
    }

    // ======================== Folder blocks (bids 0..15) ========================
    {
        // Wait for all reducers.
        if (tid == 0) {
            while (*(volatile int*)&g_red_done != NRED) {
                __nanosleep(64);
            }
            __threadfence();
        }
        __syncthreads();

        const int lane = tid & 31;
        const int wrp  = tid >> 5;           // 8 warps = 8 partial groups
        const int col  = bid * 32 + lane;    // this block's 32 float4 columns

        // Each thread folds 32 of the 256 slices (p = wrp, wrp+8, ..., wrp+248).
        float4 acc = make_float4(0.f, 0.f, 0.f, 0.f);
        #pragma unroll 8
        for (int j = 0; j < 32; ++j) {
            const float4 v = g_partial4[(wrp + 8 * j) * IN_F4 + col];
            acc.x += v.x; acc.y += v.y; acc.z += v.z; acc.w += v.w;
        }

        // Cross-warp fold via shared (reuse sw storage).
        float4* sh = sw;                     // need 8*32 float4 = 4 KB < 8 KB
        sh[wrp * 32 + lane] = acc;
        __syncthreads();
        if (wrp == 0) {
            float4 t = sh[lane];
            #pragma unroll
            for (int p = 1; p < 8; ++p) {
                const float4 v = sh[p * 32 + lane];
                t.x += v.x; t.y += v.y; t.z += v.z; t.w += v.w;
            }
            reinterpret_cast<float4*>(g_wsum)[col] = t;
            __threadfence();
        }
        __syncthreads();
        if (tid == 0) atomicAdd(&g_fold_done, 1);
        return;
    }
}

// ---------------------------------------------------------------------------
extern "C" void kernel_launch(void* const* d_in, const int* in_sizes, int n_in,
                              void* d_out, int out_size) {
    const float* x      = (const float*)d_in[0];  // (131072, 2048)
    const float* weight = (const float*)d_in[1];  // (4096, 2048)
    const float* bias   = (const float*)d_in[2];  // (4096,)
    float* out = (float*)d_out;                   // (131072, 1)

    (void)in_sizes; (void)n_in; (void)out_size;

    init_kernel<<<1, 1>>>();
    fused_kernel<<<GRID_TOTAL, 256>>>(reinterpret_cast<const float4*>(weight),
                                      x, bias, out);
}